// round 12
// baseline (speedup 1.0000x reference)
#include <cuda_runtime.h>
#include <cstdint>

#define NN    100000
#define EE    1600000
#define HIDD  128
#define INDIM 64
#define NBATCH 8
#define KTOP  5000
#define NPER  12500
#define NCLS  18
#define SORTN 16384
#define SCAN_BLOCKS 98   // ceil(100000 / 1024)

// packed f32x2 add: per-lane IEEE rn, bit-identical to scalar FADD
#define FADD2(acc, b)      asm("add.rn.f32x2 %0, %0, %1;" : "+l"(acc) : "l"(b))
#define UNPACK2(lo, hi, v) asm("mov.b64 {%0, %1}, %2;" : "=f"(lo), "=f"(hi) : "l"(v))

// smem bank swizzle for the sort
#define PHYS(i) ((i) ^ (((i) >> 4) & 15))

// 4 FMAs of scalar x into float4 acc (order: x then wv components ascending)
#define FMA4(acc, xs_, wv_) \
    acc.x += (xs_) * (wv_).x; acc.y += (xs_) * (wv_).y; \
    acc.z += (xs_) * (wv_).z; acc.w += (xs_) * (wv_).w;

// ---------------- scratch (device globals; referenced ONLY from device code) --
__device__ float g_t[(size_t)NN * HIDD];        // layer-1 scaled feats / layer-2 xW
__device__ float g_h[(size_t)NN * HIDD];        // layer output features
__device__ float g_norm_src[NN];
__device__ float g_norm_dst[NN];
__device__ int   g_deg_out[NN];
__device__ int   g_deg_in[NN];
__device__ int   g_row_start[NN + 1];
__device__ int   g_cursor[NN];
__device__ int   g_csr_src[EE];
__device__ int   g_topk[NBATCH * KTOP];
__device__ int   g_scan_agg[SCAN_BLOCKS];
__device__ int   g_scan_flag[SCAN_BLOCKS];

// ---------------- degree (launch 1) -------------------------------------------
__global__ void degree_kernel(const int* __restrict__ src, const int* __restrict__ dst) {
    int e = blockIdx.x * blockDim.x + threadIdx.x;
    if (e < EE) {
        atomicAdd(&g_deg_out[src[e]], 1);
        atomicAdd(&g_deg_in[dst[e]], 1);
    }
}

// ---------------- single-kernel scan + norms (launch 2) ------------------------
__global__ void scan_fused_kernel() {
    __shared__ int sh[1024];
    __shared__ int red[128];
    int tid = threadIdx.x, b = blockIdx.x;
    int i = b * 1024 + tid;
    int v = (i < NN) ? g_deg_in[i] : 0;

    sh[tid] = v;
    __syncthreads();
    #pragma unroll
    for (int off = 512; off > 0; off >>= 1) {
        if (tid < off) sh[tid] += sh[tid + off];
        __syncthreads();
    }
    int bsum = sh[0];
    __syncthreads();
    if (tid == 0) {
        *(volatile int*)&g_scan_agg[b] = bsum;
        __threadfence();
        *(volatile int*)&g_scan_flag[b] = 1;
    }

    if (tid < 128) {
        int val = 0;
        if (tid < b) {
            while (*(volatile int*)&g_scan_flag[tid] == 0) {}
            val = *(volatile int*)&g_scan_agg[tid];
        }
        red[tid] = val;
    }
    __syncthreads();
    #pragma unroll
    for (int off = 64; off > 0; off >>= 1) {
        if (tid < off) red[tid] += red[tid + off];
        __syncthreads();
    }
    int offset = red[0];
    __syncthreads();

    sh[tid] = v;
    __syncthreads();
    #pragma unroll
    for (int o = 1; o < 1024; o <<= 1) {
        int add = (tid >= o) ? sh[tid - o] : 0;
        __syncthreads();
        sh[tid] += add;
        __syncthreads();
    }
    if (i < NN) {
        int excl = offset + sh[tid] - v;
        g_row_start[i] = excl;
        g_cursor[i] = excl;
        g_norm_dst[i] = rsqrtf((float)max(v, 1));
        g_norm_src[i] = rsqrtf((float)max(g_deg_out[i], 1));
    }
    if (b == SCAN_BLOCKS - 1 && tid == 0)
        g_row_start[NN] = offset + bsum;
}

// ---------------- csr fill + src scaling fused (launch 3) ----------------------
__global__ void csr_scale_kernel(const int* __restrict__ src,
                                 const int* __restrict__ dst,
                                 const float* __restrict__ x) {
    int e = blockIdx.x * blockDim.x + threadIdx.x;
    if (e < EE) {
        int d = dst[e];
        int pos = atomicAdd(&g_cursor[d], 1);
        g_csr_src[pos] = src[e];
        int node = e >> 4;                    // 16 float4 per 64-float row
        float ns = g_norm_src[node];
        float4 v = *(const float4*)&x[e * 4];
        v.x *= ns; v.y *= ns; v.z *= ns; v.w *= ns;
        *(float4*)&g_t[e * 4] = v;
    }
}

// ---------------- layer-1 fused: aggregate(64) + GEMM + relu (launch 4, PROFILED)
__global__ void layer1_fused_kernel(const float* __restrict__ W,
                                    const float* __restrict__ bias) {
    extern __shared__ float sh[];
    float* Ws = sh;                  // 64*128
    float* xs = sh + 64 * 128;       // 32*64
    int tid = threadIdx.x;
    int lane = tid & 31, wid = tid >> 5;   // 8 warps
    int base = blockIdx.x * 32;

    for (int i = tid * 4; i < 64 * 128; i += 256 * 4)
        *(float4*)&Ws[i] = *(const float4*)&W[i];

    // Phase A: gather+aggregate 4 nodes per warp
    int half = lane >> 4;
    unsigned hoff = (unsigned)(lane & 15) * 4u;
    const float* tbase = (const float*)g_t;
    #pragma unroll
    for (int ni = 0; ni < 4; ni++) {
        int node = base + wid * 4 + ni;
        int s0 = g_row_start[node], s1 = g_row_start[node + 1];
        unsigned long long a0 = 0, a1 = 0, b0 = 0, b1 = 0;
        for (int bb = s0; bb < s1; bb += 32) {
            int my = (bb + lane < s1) ? g_csr_src[bb + lane] : 0;
            int cnt = min(32, s1 - bb);
            int t = 0;
            for (; t + 4 <= cnt; t += 4) {
                int sA = __shfl_sync(0xffffffffu, my, t + half);
                int sB = __shfl_sync(0xffffffffu, my, t + 2 + half);
                ulonglong2 uA = *(const ulonglong2*)&tbase[(unsigned)sA * 64u + hoff];
                ulonglong2 uB = *(const ulonglong2*)&tbase[(unsigned)sB * 64u + hoff];
                FADD2(a0, uA.x); FADD2(a1, uA.y);
                FADD2(b0, uB.x); FADD2(b1, uB.y);
            }
            for (; t + 2 <= cnt; t += 2) {
                int s = __shfl_sync(0xffffffffu, my, t + half);
                ulonglong2 u = *(const ulonglong2*)&tbase[(unsigned)s * 64u + hoff];
                FADD2(a0, u.x); FADD2(a1, u.y);
            }
            if (t < cnt) {
                int s = __shfl_sync(0xffffffffu, my, t);
                if (half == 0) {
                    ulonglong2 u = *(const ulonglong2*)&tbase[(unsigned)s * 64u + hoff];
                    FADD2(b0, u.x); FADD2(b1, u.y);
                }
            }
        }
        FADD2(a0, b0); FADD2(a1, b1);
        float4 r;
        UNPACK2(r.x, r.y, a0); UNPACK2(r.z, r.w, a1);
        r.x += __shfl_xor_sync(0xffffffffu, r.x, 16);
        r.y += __shfl_xor_sync(0xffffffffu, r.y, 16);
        r.z += __shfl_xor_sync(0xffffffffu, r.z, 16);
        r.w += __shfl_xor_sync(0xffffffffu, r.w, 16);
        if (half == 0)
            *(float4*)&xs[(unsigned)(wid * 4 + ni) * 64u + hoff] = r;
    }
    __syncthreads();

    // Phase B: GEMM, k chunked by 4 with float4 x loads (broadcast LDS.128)
    int tx = lane, ty = wid;
    float4 acc0 = make_float4(0.f, 0.f, 0.f, 0.f);
    float4 acc1 = make_float4(0.f, 0.f, 0.f, 0.f);
    float4 acc2 = make_float4(0.f, 0.f, 0.f, 0.f);
    float4 acc3 = make_float4(0.f, 0.f, 0.f, 0.f);
    const float* x0p = &xs[(ty * 4 + 0) * 64];
    const float* x1p = &xs[(ty * 4 + 1) * 64];
    const float* x2p = &xs[(ty * 4 + 2) * 64];
    const float* x3p = &xs[(ty * 4 + 3) * 64];
    #pragma unroll 2
    for (int kc = 0; kc < 64; kc += 4) {
        float4 xv0 = *(const float4*)&x0p[kc];
        float4 xv1 = *(const float4*)&x1p[kc];
        float4 xv2 = *(const float4*)&x2p[kc];
        float4 xv3 = *(const float4*)&x3p[kc];
        const float* wb = &Ws[kc * 128 + tx * 4];
        float4 wv0 = *(const float4*)&wb[0];
        float4 wv1 = *(const float4*)&wb[128];
        float4 wv2 = *(const float4*)&wb[256];
        float4 wv3 = *(const float4*)&wb[384];
        FMA4(acc0, xv0.x, wv0); FMA4(acc1, xv1.x, wv0);
        FMA4(acc2, xv2.x, wv0); FMA4(acc3, xv3.x, wv0);
        FMA4(acc0, xv0.y, wv1); FMA4(acc1, xv1.y, wv1);
        FMA4(acc2, xv2.y, wv1); FMA4(acc3, xv3.y, wv1);
        FMA4(acc0, xv0.z, wv2); FMA4(acc1, xv1.z, wv2);
        FMA4(acc2, xv2.z, wv2); FMA4(acc3, xv3.z, wv2);
        FMA4(acc0, xv0.w, wv3); FMA4(acc1, xv1.w, wv3);
        FMA4(acc2, xv2.w, wv3); FMA4(acc3, xv3.w, wv3);
    }

    int n0 = base + ty * 4;
    float4 accs[4] = {acc0, acc1, acc2, acc3};
    float4 b = *(const float4*)&bias[tx * 4];
    #pragma unroll
    for (int i = 0; i < 4; i++) {
        float nd = g_norm_dst[n0 + i];
        float4 a = accs[i];
        float4 r;
        r.x = fmaxf(a.x * nd + b.x, 0.f);
        r.y = fmaxf(a.y * nd + b.y, 0.f);
        r.z = fmaxf(a.z * nd + b.z, 0.f);
        r.w = fmaxf(a.w * nd + b.w, 0.f);
        *(float4*)&g_h[(size_t)(n0 + i) * 128 + tx * 4] = r;
    }
}

// ---------------- transform (layer 2): vectorized-x GEMM, EPI=norm_src -> g_t -
__global__ void transform2_kernel(const float* __restrict__ W) {
    extern __shared__ float sh[];
    float* Ws = sh;                  // 128*128
    float* xs = sh + 128 * 128;      // 32*128
    int tx = threadIdx.x, ty = threadIdx.y;
    int tid = ty * 32 + tx;          // 0..255
    for (int i = tid * 4; i < 128 * 128; i += 256 * 4)
        *(float4*)&Ws[i] = *(const float4*)&W[i];
    int base = blockIdx.x * 32;
    for (int i = tid * 4; i < 32 * 128; i += 256 * 4)
        *(float4*)&xs[i] = *(const float4*)&g_h[(size_t)base * 128 + i];
    __syncthreads();

    float4 acc0 = make_float4(0.f, 0.f, 0.f, 0.f);
    float4 acc1 = make_float4(0.f, 0.f, 0.f, 0.f);
    float4 acc2 = make_float4(0.f, 0.f, 0.f, 0.f);
    float4 acc3 = make_float4(0.f, 0.f, 0.f, 0.f);
    const float* x0p = &xs[(ty * 4 + 0) * 128];
    const float* x1p = &xs[(ty * 4 + 1) * 128];
    const float* x2p = &xs[(ty * 4 + 2) * 128];
    const float* x3p = &xs[(ty * 4 + 3) * 128];
    #pragma unroll 2
    for (int kc = 0; kc < 128; kc += 4) {
        float4 xv0 = *(const float4*)&x0p[kc];
        float4 xv1 = *(const float4*)&x1p[kc];
        float4 xv2 = *(const float4*)&x2p[kc];
        float4 xv3 = *(const float4*)&x3p[kc];
        const float* wb = &Ws[kc * 128 + tx * 4];
        float4 wv0 = *(const float4*)&wb[0];
        float4 wv1 = *(const float4*)&wb[128];
        float4 wv2 = *(const float4*)&wb[256];
        float4 wv3 = *(const float4*)&wb[384];
        FMA4(acc0, xv0.x, wv0); FMA4(acc1, xv1.x, wv0);
        FMA4(acc2, xv2.x, wv0); FMA4(acc3, xv3.x, wv0);
        FMA4(acc0, xv0.y, wv1); FMA4(acc1, xv1.y, wv1);
        FMA4(acc2, xv2.y, wv1); FMA4(acc3, xv3.y, wv1);
        FMA4(acc0, xv0.z, wv2); FMA4(acc1, xv1.z, wv2);
        FMA4(acc2, xv2.z, wv2); FMA4(acc3, xv3.z, wv2);
        FMA4(acc0, xv0.w, wv3); FMA4(acc1, xv1.w, wv3);
        FMA4(acc2, xv2.w, wv3); FMA4(acc3, xv3.w, wv3);
    }

    int n0 = base + ty * 4;
    float4 accs[4] = {acc0, acc1, acc2, acc3};
    #pragma unroll
    for (int i = 0; i < 4; i++) {
        float ns = g_norm_src[n0 + i];
        float4 a = accs[i];
        a.x *= ns; a.y *= ns; a.z *= ns; a.w *= ns;
        *(float4*)&g_t[(size_t)(n0 + i) * 128 + tx * 4] = a;
    }
}

// ---------------- 128-dim aggregate (layer 2): packed f32x2 adds ---------------
__global__ void aggregate_kernel(const float* __restrict__ bias) {
    int gtid = blockIdx.x * blockDim.x + threadIdx.x;
    int node = gtid >> 5;
    int lane = gtid & 31;
    if (node >= NN) return;
    unsigned loff = (unsigned)lane * 4u;
    int s0 = g_row_start[node], s1 = g_row_start[node + 1];
    unsigned long long a0 = 0, a1 = 0, b0 = 0, b1 = 0;
    const float* tbase = (const float*)g_t;
    for (int base = s0; base < s1; base += 32) {
        int my = (base + lane < s1) ? g_csr_src[base + lane] : 0;
        int cnt = min(32, s1 - base);
        int t = 0;
        for (; t + 2 <= cnt; t += 2) {
            int sA = __shfl_sync(0xffffffffu, my, t);
            int sB = __shfl_sync(0xffffffffu, my, t + 1);
            ulonglong2 uA = *(const ulonglong2*)&tbase[(unsigned)sA * 128u + loff];
            ulonglong2 uB = *(const ulonglong2*)&tbase[(unsigned)sB * 128u + loff];
            FADD2(a0, uA.x); FADD2(a1, uA.y);
            FADD2(b0, uB.x); FADD2(b1, uB.y);
        }
        if (t < cnt) {
            int s = __shfl_sync(0xffffffffu, my, t);
            ulonglong2 u = *(const ulonglong2*)&tbase[(unsigned)s * 128u + loff];
            FADD2(a0, u.x); FADD2(a1, u.y);
        }
    }
    FADD2(a0, b0); FADD2(a1, b1);
    float4 acc;
    UNPACK2(acc.x, acc.y, a0); UNPACK2(acc.z, acc.w, a1);
    float nd = g_norm_dst[node];
    float4 b = *(const float4*)&bias[loff];
    float4 r;
    r.x = fmaxf(acc.x * nd + b.x, 0.f);
    r.y = fmaxf(acc.y * nd + b.y, 0.f);
    r.z = fmaxf(acc.z * nd + b.z, 0.f);
    r.w = fmaxf(acc.w * nd + b.w, 0.f);
    *(float4*)&g_h[(unsigned)node * 128u + loff] = r;
}

// ---------------- top-K: register-tiled bitonic sort ---------------------------
__global__ void topk_kernel(const float* __restrict__ b3, float* __restrict__ out) {
    extern __shared__ unsigned long long s[];
    int b = blockIdx.x;
    int tid = threadIdx.x;
    if (b == 0 && tid < NBATCH * NCLS)
        out[tid] = b3[tid % NCLS];

    for (int i = tid; i < SORTN; i += 1024) {
        unsigned long long key;
        if (i < NPER) {
            float f = g_h[((size_t)(b * NPER + i)) * 128 + 127];
            unsigned bits = __float_as_uint(f);
            unsigned m = ((int)bits < 0) ? ~bits : (bits ^ 0x80000000u);
            key = (((unsigned long long)(~m)) << 32) | (unsigned)i;
        } else {
            key = 0xFFFFFFFFFFFFFFFFull;
        }
        s[PHYS(i)] = key;
    }
    __syncthreads();

    unsigned long long r[16];
    int base16 = tid * 16;

    #pragma unroll
    for (int i = 0; i < 16; i++) r[i] = s[PHYS(base16 + i)];
    #pragma unroll
    for (int k = 2; k <= 16; k <<= 1) {
        #pragma unroll
        for (int j = k >> 1; j > 0; j >>= 1) {
            #pragma unroll
            for (int i = 0; i < 16; i++) {
                if ((i & j) == 0) {
                    bool up = (((base16 + i) & k) == 0);
                    unsigned long long lo = r[i], hi = r[i | j];
                    if ((lo > hi) == up) { r[i] = hi; r[i | j] = lo; }
                }
            }
        }
    }
    #pragma unroll
    for (int i = 0; i < 16; i++) s[PHYS(base16 + i)] = r[i];
    __syncthreads();

    for (int k = 32; k <= SORTN; k <<= 1) {
        for (int j = k >> 1; j >= 16; j >>= 1) {
            #pragma unroll
            for (int q = 0; q < SORTN / 2 / 1024; q++) {
                int p = tid + q * 1024;
                int idx = ((p & ~(j - 1)) << 1) | (p & (j - 1));
                int partner = idx + j;
                bool up = ((idx & k) == 0);
                unsigned long long a = s[PHYS(idx)], c = s[PHYS(partner)];
                if ((a > c) == up) { s[PHYS(idx)] = c; s[PHYS(partner)] = a; }
            }
            __syncthreads();
        }
        {
            bool up = ((base16 & k) == 0);
            #pragma unroll
            for (int i = 0; i < 16; i++) r[i] = s[PHYS(base16 + i)];
            #pragma unroll
            for (int j = 8; j > 0; j >>= 1) {
                #pragma unroll
                for (int i = 0; i < 16; i++) {
                    if ((i & j) == 0) {
                        unsigned long long lo = r[i], hi = r[i | j];
                        if ((lo > hi) == up) { r[i] = hi; r[i | j] = lo; }
                    }
                }
            }
            #pragma unroll
            for (int i = 0; i < 16; i++) s[PHYS(base16 + i)] = r[i];
            __syncthreads();
        }
    }

    for (int i = tid; i < KTOP; i += 1024) {
        int local = (int)(s[PHYS(i)] & 0xFFFFFFFFu);
        g_topk[b * KTOP + i] = b * NPER + local;
    }
}

// ---------------- readout ------------------------------------------------------
__global__ void final_gemm_kernel(const float* __restrict__ W3, float* __restrict__ out) {
    int w = threadIdx.x >> 5, lane = threadIdx.x & 31;
    const int KTOT = KTOP * 128;
    int per = KTOT / gridDim.x;
    int k0 = blockIdx.x * per, k1 = k0 + per;
    float acc[NCLS];
    #pragma unroll
    for (int c = 0; c < NCLS; c++) acc[c] = 0.f;
    for (int k = k0 + lane; k < k1; k += 32) {
        int i = k >> 7, h = k & 127;
        int node = g_topk[w * KTOP + i];
        float x = g_h[(size_t)node * 128 + h];
        const float* wrow = &W3[(size_t)k * NCLS];
        #pragma unroll
        for (int c = 0; c < NCLS; c++) acc[c] += x * wrow[c];
    }
    #pragma unroll
    for (int c = 0; c < NCLS; c++) {
        float v = acc[c];
        #pragma unroll
        for (int o = 16; o > 0; o >>= 1) v += __shfl_down_sync(0xffffffffu, v, o);
        if (lane == 0) atomicAdd(&out[w * NCLS + c], v);
    }
}

// ---------------- launch ------------------------------------------------------
extern "C" void kernel_launch(void* const* d_in, const int* in_sizes, int n_in,
                              void* d_out, int out_size) {
    const float* features = (const float*)d_in[0];
    const int*   src      = (const int*)d_in[1];
    const int*   dst      = (const int*)d_in[2];
    const float* W1       = (const float*)d_in[3];
    const float* b1       = (const float*)d_in[4];
    const float* W2       = (const float*)d_in[5];
    const float* b2       = (const float*)d_in[6];
    const float* W3       = (const float*)d_in[7];
    const float* b3       = (const float*)d_in[8];
    float* out = (float*)d_out;

    const int smem_l1 = (64 * 128 + 32 * 64) * 4;    // 40 KB
    const int smem_t2 = (128 * 128 + 32 * 128) * 4;  // 80 KB
    cudaFuncSetAttribute(layer1_fused_kernel,
        cudaFuncAttributeMaxDynamicSharedMemorySize, smem_l1);
    cudaFuncSetAttribute(transform2_kernel,
        cudaFuncAttributeMaxDynamicSharedMemorySize, smem_t2);
    cudaFuncSetAttribute(topk_kernel,
        cudaFuncAttributeMaxDynamicSharedMemorySize, SORTN * 8);

    void* deg_out_addr = nullptr;
    void* deg_in_addr = nullptr;
    void* flag_addr = nullptr;
    cudaGetSymbolAddress(&deg_out_addr, g_deg_out);
    cudaGetSymbolAddress(&deg_in_addr, g_deg_in);
    cudaGetSymbolAddress(&flag_addr, g_scan_flag);
    cudaMemsetAsync(deg_out_addr, 0, NN * sizeof(int));
    cudaMemsetAsync(deg_in_addr, 0, NN * sizeof(int));
    cudaMemsetAsync(flag_addr, 0, SCAN_BLOCKS * sizeof(int));

    degree_kernel<<<(EE + 255) / 256, 256>>>(src, dst);
    scan_fused_kernel<<<SCAN_BLOCKS, 1024>>>();
    csr_scale_kernel<<<(EE + 255) / 256, 256>>>(src, dst, features);

    // launch 4 (PROFILED): fused layer-1 aggregate + GEMM + relu
    layer1_fused_kernel<<<NN / 32, 256, smem_l1>>>(W1, b1);

    dim3 tblock(32, 8);
    transform2_kernel<<<NN / 32, tblock, smem_t2>>>(W2);
    aggregate_kernel<<<(NN * 32 + 255) / 256, 256>>>(b2);

    topk_kernel<<<NBATCH, 1024, SORTN * 8>>>(b3, out);
    final_gemm_kernel<<<250, 256>>>(W3, out);
}

// round 14
// speedup vs baseline: 1.0831x; 1.0831x over previous
#include <cuda_runtime.h>
#include <cstdint>

#define NN    100000
#define EE    1600000
#define HIDD  128
#define INDIM 64
#define NBATCH 8
#define KTOP  5000
#define NPER  12500
#define NCLS  18
#define SORTN 16384
#define TILE  2048
#define SCAN_BLOCKS 98   // ceil(100000 / 1024)

// packed f32x2 add: per-lane IEEE rn, bit-identical to scalar FADD
#define FADD2(acc, b)      asm("add.rn.f32x2 %0, %0, %1;" : "+l"(acc) : "l"(b))
#define UNPACK2(lo, hi, v) asm("mov.b64 {%0, %1}, %2;" : "=f"(lo), "=f"(hi) : "l"(v))

// smem bank swizzle for the sort (alters only low 4 bits; bijective in-tile)
#define PHYS(i) ((i) ^ (((i) >> 4) & 15))

// 4 FMAs of scalar x into float4 acc
#define FMA4(acc, xs_, wv_) \
    acc.x += (xs_) * (wv_).x; acc.y += (xs_) * (wv_).y; \
    acc.z += (xs_) * (wv_).z; acc.w += (xs_) * (wv_).w;

// ---------------- scratch (device globals; referenced ONLY from device code) --
__device__ float g_t[(size_t)NN * HIDD];
__device__ float g_h[(size_t)NN * HIDD];
__device__ float g_norm_src[NN];
__device__ float g_norm_dst[NN];
__device__ int   g_deg_out[NN];
__device__ int   g_deg_in[NN];
__device__ int   g_row_start[NN + 1];
__device__ int   g_cursor[NN];
__device__ int   g_csr_src[EE];
__device__ int   g_topk[NBATCH * KTOP];
__device__ int   g_scan_agg[SCAN_BLOCKS];
__device__ int   g_scan_flag[SCAN_BLOCKS];
__device__ unsigned long long g_keys[NBATCH * SORTN];   // 1 MB sort scratch

// ---------------- degree (launch 1) -------------------------------------------
__global__ void degree_kernel(const int* __restrict__ src, const int* __restrict__ dst) {
    int e = blockIdx.x * blockDim.x + threadIdx.x;
    if (e < EE) {
        atomicAdd(&g_deg_out[src[e]], 1);
        atomicAdd(&g_deg_in[dst[e]], 1);
    }
}

// ---------------- single-kernel scan + norms (launch 2) ------------------------
__global__ void scan_fused_kernel() {
    __shared__ int sh[1024];
    __shared__ int red[128];
    int tid = threadIdx.x, b = blockIdx.x;
    int i = b * 1024 + tid;
    int v = (i < NN) ? g_deg_in[i] : 0;

    sh[tid] = v;
    __syncthreads();
    #pragma unroll
    for (int off = 512; off > 0; off >>= 1) {
        if (tid < off) sh[tid] += sh[tid + off];
        __syncthreads();
    }
    int bsum = sh[0];
    __syncthreads();
    if (tid == 0) {
        *(volatile int*)&g_scan_agg[b] = bsum;
        __threadfence();
        *(volatile int*)&g_scan_flag[b] = 1;
    }

    if (tid < 128) {
        int val = 0;
        if (tid < b) {
            while (*(volatile int*)&g_scan_flag[tid] == 0) {}
            val = *(volatile int*)&g_scan_agg[tid];
        }
        red[tid] = val;
    }
    __syncthreads();
    #pragma unroll
    for (int off = 64; off > 0; off >>= 1) {
        if (tid < off) red[tid] += red[tid + off];
        __syncthreads();
    }
    int offset = red[0];
    __syncthreads();

    sh[tid] = v;
    __syncthreads();
    #pragma unroll
    for (int o = 1; o < 1024; o <<= 1) {
        int add = (tid >= o) ? sh[tid - o] : 0;
        __syncthreads();
        sh[tid] += add;
        __syncthreads();
    }
    if (i < NN) {
        int excl = offset + sh[tid] - v;
        g_row_start[i] = excl;
        g_cursor[i] = excl;
        g_norm_dst[i] = rsqrtf((float)max(v, 1));
        g_norm_src[i] = rsqrtf((float)max(g_deg_out[i], 1));
    }
    if (b == SCAN_BLOCKS - 1 && tid == 0)
        g_row_start[NN] = offset + bsum;
}

// ---------------- csr fill + src scaling fused (launch 3) ----------------------
__global__ void csr_scale_kernel(const int* __restrict__ src,
                                 const int* __restrict__ dst,
                                 const float* __restrict__ x) {
    int e = blockIdx.x * blockDim.x + threadIdx.x;
    if (e < EE) {
        int d = dst[e];
        int pos = atomicAdd(&g_cursor[d], 1);
        g_csr_src[pos] = src[e];
        int node = e >> 4;
        float ns = g_norm_src[node];
        float4 v = *(const float4*)&x[e * 4];
        v.x *= ns; v.y *= ns; v.z *= ns; v.w *= ns;
        *(float4*)&g_t[e * 4] = v;
    }
}

// ---------------- layer-1 fused: aggregate(64) + GEMM + relu (launch 4) --------
__global__ void layer1_fused_kernel(const float* __restrict__ W,
                                    const float* __restrict__ bias) {
    extern __shared__ float sh[];
    float* Ws = sh;                  // 64*128
    float* xs = sh + 64 * 128;       // 32*64
    int tid = threadIdx.x;
    int lane = tid & 31, wid = tid >> 5;
    int base = blockIdx.x * 32;

    for (int i = tid * 4; i < 64 * 128; i += 256 * 4)
        *(float4*)&Ws[i] = *(const float4*)&W[i];

    // Phase A: gather+aggregate 4 nodes per warp (half-warp rows)
    int half = lane >> 4;
    unsigned hoff = (unsigned)(lane & 15) * 4u;
    const float* tbase = (const float*)g_t;
    #pragma unroll
    for (int ni = 0; ni < 4; ni++) {
        int node = base + wid * 4 + ni;
        int s0 = g_row_start[node], s1 = g_row_start[node + 1];
        unsigned long long a0 = 0, a1 = 0, b0 = 0, b1 = 0;
        for (int bb = s0; bb < s1; bb += 32) {
            int my = (bb + lane < s1) ? g_csr_src[bb + lane] : 0;
            int cnt = min(32, s1 - bb);
            int t = 0;
            for (; t + 4 <= cnt; t += 4) {
                int sA = __shfl_sync(0xffffffffu, my, t + half);
                int sB = __shfl_sync(0xffffffffu, my, t + 2 + half);
                ulonglong2 uA = *(const ulonglong2*)&tbase[(unsigned)sA * 64u + hoff];
                ulonglong2 uB = *(const ulonglong2*)&tbase[(unsigned)sB * 64u + hoff];
                FADD2(a0, uA.x); FADD2(a1, uA.y);
                FADD2(b0, uB.x); FADD2(b1, uB.y);
            }
            for (; t + 2 <= cnt; t += 2) {
                int s = __shfl_sync(0xffffffffu, my, t + half);
                ulonglong2 u = *(const ulonglong2*)&tbase[(unsigned)s * 64u + hoff];
                FADD2(a0, u.x); FADD2(a1, u.y);
            }
            if (t < cnt) {
                int s = __shfl_sync(0xffffffffu, my, t);
                if (half == 0) {
                    ulonglong2 u = *(const ulonglong2*)&tbase[(unsigned)s * 64u + hoff];
                    FADD2(b0, u.x); FADD2(b1, u.y);
                }
            }
        }
        FADD2(a0, b0); FADD2(a1, b1);
        float4 r;
        UNPACK2(r.x, r.y, a0); UNPACK2(r.z, r.w, a1);
        r.x += __shfl_xor_sync(0xffffffffu, r.x, 16);
        r.y += __shfl_xor_sync(0xffffffffu, r.y, 16);
        r.z += __shfl_xor_sync(0xffffffffu, r.z, 16);
        r.w += __shfl_xor_sync(0xffffffffu, r.w, 16);
        if (half == 0)
            *(float4*)&xs[(unsigned)(wid * 4 + ni) * 64u + hoff] = r;
    }
    __syncthreads();

    // Phase B: GEMM (scalar-x form — 43 regs, 5 blocks/SM)
    int tx = lane, ty = wid;
    float4 acc0 = make_float4(0.f, 0.f, 0.f, 0.f);
    float4 acc1 = make_float4(0.f, 0.f, 0.f, 0.f);
    float4 acc2 = make_float4(0.f, 0.f, 0.f, 0.f);
    float4 acc3 = make_float4(0.f, 0.f, 0.f, 0.f);
    const float* x0p = &xs[(ty * 4 + 0) * 64];
    const float* x1p = &xs[(ty * 4 + 1) * 64];
    const float* x2p = &xs[(ty * 4 + 2) * 64];
    const float* x3p = &xs[(ty * 4 + 3) * 64];
    #pragma unroll 8
    for (int k = 0; k < 64; k++) {
        float4 wv = *(const float4*)&Ws[k * 128 + tx * 4];
        float x0 = x0p[k], x1 = x1p[k], x2 = x2p[k], x3 = x3p[k];
        FMA4(acc0, x0, wv); FMA4(acc1, x1, wv);
        FMA4(acc2, x2, wv); FMA4(acc3, x3, wv);
    }

    int n0 = base + ty * 4;
    float4 accs[4] = {acc0, acc1, acc2, acc3};
    float4 b = *(const float4*)&bias[tx * 4];
    #pragma unroll
    for (int i = 0; i < 4; i++) {
        float nd = g_norm_dst[n0 + i];
        float4 a = accs[i];
        float4 r;
        r.x = fmaxf(a.x * nd + b.x, 0.f);
        r.y = fmaxf(a.y * nd + b.y, 0.f);
        r.z = fmaxf(a.z * nd + b.z, 0.f);
        r.w = fmaxf(a.w * nd + b.w, 0.f);
        *(float4*)&g_h[(size_t)(n0 + i) * 128 + tx * 4] = r;
    }
}

// ---------------- transform (layer 2): vectorized-x GEMM -> g_t ---------------
__global__ void transform2_kernel(const float* __restrict__ W) {
    extern __shared__ float sh[];
    float* Ws = sh;                  // 128*128
    float* xs = sh + 128 * 128;      // 32*128
    int tx = threadIdx.x, ty = threadIdx.y;
    int tid = ty * 32 + tx;
    for (int i = tid * 4; i < 128 * 128; i += 256 * 4)
        *(float4*)&Ws[i] = *(const float4*)&W[i];
    int base = blockIdx.x * 32;
    for (int i = tid * 4; i < 32 * 128; i += 256 * 4)
        *(float4*)&xs[i] = *(const float4*)&g_h[(size_t)base * 128 + i];
    __syncthreads();

    float4 acc0 = make_float4(0.f, 0.f, 0.f, 0.f);
    float4 acc1 = make_float4(0.f, 0.f, 0.f, 0.f);
    float4 acc2 = make_float4(0.f, 0.f, 0.f, 0.f);
    float4 acc3 = make_float4(0.f, 0.f, 0.f, 0.f);
    const float* x0p = &xs[(ty * 4 + 0) * 128];
    const float* x1p = &xs[(ty * 4 + 1) * 128];
    const float* x2p = &xs[(ty * 4 + 2) * 128];
    const float* x3p = &xs[(ty * 4 + 3) * 128];
    #pragma unroll 2
    for (int kc = 0; kc < 128; kc += 4) {
        float4 xv0 = *(const float4*)&x0p[kc];
        float4 xv1 = *(const float4*)&x1p[kc];
        float4 xv2 = *(const float4*)&x2p[kc];
        float4 xv3 = *(const float4*)&x3p[kc];
        const float* wb = &Ws[kc * 128 + tx * 4];
        float4 wv0 = *(const float4*)&wb[0];
        float4 wv1 = *(const float4*)&wb[128];
        float4 wv2 = *(const float4*)&wb[256];
        float4 wv3 = *(const float4*)&wb[384];
        FMA4(acc0, xv0.x, wv0); FMA4(acc1, xv1.x, wv0);
        FMA4(acc2, xv2.x, wv0); FMA4(acc3, xv3.x, wv0);
        FMA4(acc0, xv0.y, wv1); FMA4(acc1, xv1.y, wv1);
        FMA4(acc2, xv2.y, wv1); FMA4(acc3, xv3.y, wv1);
        FMA4(acc0, xv0.z, wv2); FMA4(acc1, xv1.z, wv2);
        FMA4(acc2, xv2.z, wv2); FMA4(acc3, xv3.z, wv2);
        FMA4(acc0, xv0.w, wv3); FMA4(acc1, xv1.w, wv3);
        FMA4(acc2, xv2.w, wv3); FMA4(acc3, xv3.w, wv3);
    }

    int n0 = base + ty * 4;
    float4 accs[4] = {acc0, acc1, acc2, acc3};
    #pragma unroll
    for (int i = 0; i < 4; i++) {
        float ns = g_norm_src[n0 + i];
        float4 a = accs[i];
        a.x *= ns; a.y *= ns; a.z *= ns; a.w *= ns;
        *(float4*)&g_t[(size_t)(n0 + i) * 128 + tx * 4] = a;
    }
}

// ---------------- 128-dim aggregate (layer 2) ----------------------------------
__global__ void aggregate_kernel(const float* __restrict__ bias) {
    int gtid = blockIdx.x * blockDim.x + threadIdx.x;
    int node = gtid >> 5;
    int lane = gtid & 31;
    if (node >= NN) return;
    unsigned loff = (unsigned)lane * 4u;
    int s0 = g_row_start[node], s1 = g_row_start[node + 1];
    unsigned long long a0 = 0, a1 = 0, b0 = 0, b1 = 0;
    const float* tbase = (const float*)g_t;
    for (int base = s0; base < s1; base += 32) {
        int my = (base + lane < s1) ? g_csr_src[base + lane] : 0;
        int cnt = min(32, s1 - base);
        int t = 0;
        for (; t + 2 <= cnt; t += 2) {
            int sA = __shfl_sync(0xffffffffu, my, t);
            int sB = __shfl_sync(0xffffffffu, my, t + 1);
            ulonglong2 uA = *(const ulonglong2*)&tbase[(unsigned)sA * 128u + loff];
            ulonglong2 uB = *(const ulonglong2*)&tbase[(unsigned)sB * 128u + loff];
            FADD2(a0, uA.x); FADD2(a1, uA.y);
            FADD2(b0, uB.x); FADD2(b1, uB.y);
        }
        if (t < cnt) {
            int s = __shfl_sync(0xffffffffu, my, t);
            ulonglong2 u = *(const ulonglong2*)&tbase[(unsigned)s * 128u + loff];
            FADD2(a0, u.x); FADD2(a1, u.y);
        }
    }
    FADD2(a0, b0); FADD2(a1, b1);
    float4 acc;
    UNPACK2(acc.x, acc.y, a0); UNPACK2(acc.z, acc.w, a1);
    float nd = g_norm_dst[node];
    float4 b = *(const float4*)&bias[loff];
    float4 r;
    r.x = fmaxf(acc.x * nd + b.x, 0.f);
    r.y = fmaxf(acc.y * nd + b.y, 0.f);
    r.z = fmaxf(acc.z * nd + b.z, 0.f);
    r.w = fmaxf(acc.w * nd + b.w, 0.f);
    *(float4*)&g_h[(unsigned)node * 128u + loff] = r;
}

// =================== hybrid bitonic top-K (same network, spread over 64 blocks)
// Direction everywhere: up = ((global_idx & k) == 0) — identical to the
// monolithic network, so the result is bit-identical.

// local sort of one tile through stage k=2048 (+ fused out init, strided!)
__global__ void topk_local_kernel(const float* __restrict__ b3, float* __restrict__ out) {
    __shared__ unsigned long long s[TILE];
    int blk = blockIdx.x;
    int b = blk >> 3, t = blk & 7;
    int tid = threadIdx.x;            // 128 threads
    int gbase = t * TILE;
    if (blk == 0) {
        for (int i = tid; i < NBATCH * NCLS; i += 128)   // FIXED: strided init
            out[i] = b3[i % NCLS];
    }

    for (int i = tid; i < TILE; i += 128) {
        int gi = gbase + i;
        unsigned long long key;
        if (gi < NPER) {
            float f = g_h[((size_t)(b * NPER + gi)) * 128 + 127];
            unsigned bits = __float_as_uint(f);
            unsigned m = ((int)bits < 0) ? ~bits : (bits ^ 0x80000000u);
            key = (((unsigned long long)(~m)) << 32) | (unsigned)gi;
        } else {
            key = 0xFFFFFFFFFFFFFFFFull;
        }
        s[PHYS(i)] = key;
    }
    __syncthreads();

    unsigned long long r[16];
    int base16 = tid * 16;

    // stages k=2..16 in registers
    #pragma unroll
    for (int i = 0; i < 16; i++) r[i] = s[PHYS(base16 + i)];
    #pragma unroll
    for (int k = 2; k <= 16; k <<= 1) {
        #pragma unroll
        for (int j = k >> 1; j > 0; j >>= 1) {
            #pragma unroll
            for (int i = 0; i < 16; i++) {
                if ((i & j) == 0) {
                    bool up = (((gbase + base16 + i) & k) == 0);
                    unsigned long long lo = r[i], hi = r[i | j];
                    if ((lo > hi) == up) { r[i] = hi; r[i | j] = lo; }
                }
            }
        }
    }
    #pragma unroll
    for (int i = 0; i < 16; i++) s[PHYS(base16 + i)] = r[i];
    __syncthreads();

    // stages k=32..2048: smem phases j>=16, register tail j<=8
    for (int k = 32; k <= TILE; k <<= 1) {
        for (int j = k >> 1; j >= 16; j >>= 1) {
            #pragma unroll
            for (int q = 0; q < TILE / 2 / 128; q++) {
                int p = tid + q * 128;
                int idx = ((p & ~(j - 1)) << 1) | (p & (j - 1));
                int partner = idx + j;
                bool up = (((gbase + idx) & k) == 0);
                unsigned long long a = s[PHYS(idx)], c = s[PHYS(partner)];
                if ((a > c) == up) { s[PHYS(idx)] = c; s[PHYS(partner)] = a; }
            }
            __syncthreads();
        }
        {
            bool up = (((gbase + base16) & k) == 0);
            #pragma unroll
            for (int i = 0; i < 16; i++) r[i] = s[PHYS(base16 + i)];
            #pragma unroll
            for (int j = 8; j > 0; j >>= 1) {
                #pragma unroll
                for (int i = 0; i < 16; i++) {
                    if ((i & j) == 0) {
                        unsigned long long lo = r[i], hi = r[i | j];
                        if ((lo > hi) == up) { r[i] = hi; r[i | j] = lo; }
                    }
                }
            }
            #pragma unroll
            for (int i = 0; i < 16; i++) s[PHYS(base16 + i)] = r[i];
            __syncthreads();
        }
    }

    for (int i = tid; i < TILE; i += 128)
        g_keys[b * SORTN + gbase + i] = s[PHYS(i)];
}

// one cross-tile phase (j >= 2048) in global memory
__global__ void topk_global_phase_kernel(int k, int j) {
    int gt = blockIdx.x * blockDim.x + threadIdx.x;   // 8 * 8192 threads
    int b = gt >> 13;
    int p = gt & 8191;
    int idx = ((p & ~(j - 1)) << 1) | (p & (j - 1));
    int partner = idx + j;
    bool up = ((idx & k) == 0);
    unsigned long long* keys = &g_keys[(size_t)b * SORTN];
    unsigned long long a = keys[idx], c = keys[partner];
    if ((a > c) == up) { keys[idx] = c; keys[partner] = a; }
}

// per-tile merge: phases j=1024..1 of stage KSTAGE (direction constant per tile)
template <int KSTAGE, bool FINAL>
__global__ void topk_merge_kernel() {
    __shared__ unsigned long long s[TILE];
    int blk = blockIdx.x;
    int b = blk >> 3, t = blk & 7;
    int tid = threadIdx.x;            // 128 threads
    int gbase = t * TILE;
    const bool up = ((gbase & KSTAGE) == 0);

    for (int i = tid; i < TILE; i += 128)
        s[PHYS(i)] = g_keys[b * SORTN + gbase + i];
    __syncthreads();

    for (int j = 1024; j >= 16; j >>= 1) {
        #pragma unroll
        for (int q = 0; q < TILE / 2 / 128; q++) {
            int p = tid + q * 128;
            int idx = ((p & ~(j - 1)) << 1) | (p & (j - 1));
            int partner = idx + j;
            unsigned long long a = s[PHYS(idx)], c = s[PHYS(partner)];
            if ((a > c) == up) { s[PHYS(idx)] = c; s[PHYS(partner)] = a; }
        }
        __syncthreads();
    }

    unsigned long long r[16];
    int base16 = tid * 16;
    #pragma unroll
    for (int i = 0; i < 16; i++) r[i] = s[PHYS(base16 + i)];
    #pragma unroll
    for (int j = 8; j > 0; j >>= 1) {
        #pragma unroll
        for (int i = 0; i < 16; i++) {
            if ((i & j) == 0) {
                unsigned long long lo = r[i], hi = r[i | j];
                if ((lo > hi) == up) { r[i] = hi; r[i | j] = lo; }
            }
        }
    }
    if (FINAL) {
        #pragma unroll
        for (int i = 0; i < 16; i++) {
            int gpos = gbase + base16 + i;
            if (gpos < KTOP)
                g_topk[b * KTOP + gpos] = b * NPER + (int)(r[i] & 0xFFFFFFFFu);
        }
    } else {
        #pragma unroll
        for (int i = 0; i < 16; i++)
            g_keys[b * SORTN + gbase + base16 + i] = r[i];
    }
}

// ---------------- readout ------------------------------------------------------
__global__ void final_gemm_kernel(const float* __restrict__ W3, float* __restrict__ out) {
    int w = threadIdx.x >> 5, lane = threadIdx.x & 31;
    const int KTOT = KTOP * 128;
    int per = KTOT / gridDim.x;
    int k0 = blockIdx.x * per, k1 = k0 + per;
    float acc[NCLS];
    #pragma unroll
    for (int c = 0; c < NCLS; c++) acc[c] = 0.f;
    for (int k = k0 + lane; k < k1; k += 32) {
        int i = k >> 7, h = k & 127;
        int node = g_topk[w * KTOP + i];
        float x = g_h[(size_t)node * 128 + h];
        const float* wrow = &W3[(size_t)k * NCLS];
        #pragma unroll
        for (int c = 0; c < NCLS; c++) acc[c] += x * wrow[c];
    }
    #pragma unroll
    for (int c = 0; c < NCLS; c++) {
        float v = acc[c];
        #pragma unroll
        for (int o = 16; o > 0; o >>= 1) v += __shfl_down_sync(0xffffffffu, v, o);
        if (lane == 0) atomicAdd(&out[w * NCLS + c], v);
    }
}

// ---------------- launch ------------------------------------------------------
extern "C" void kernel_launch(void* const* d_in, const int* in_sizes, int n_in,
                              void* d_out, int out_size) {
    const float* features = (const float*)d_in[0];
    const int*   src      = (const int*)d_in[1];
    const int*   dst      = (const int*)d_in[2];
    const float* W1       = (const float*)d_in[3];
    const float* b1       = (const float*)d_in[4];
    const float* W2       = (const float*)d_in[5];
    const float* b2       = (const float*)d_in[6];
    const float* W3       = (const float*)d_in[7];
    const float* b3       = (const float*)d_in[8];
    float* out = (float*)d_out;

    const int smem_l1 = (64 * 128 + 32 * 64) * 4;    // 40 KB
    const int smem_t2 = (128 * 128 + 32 * 128) * 4;  // 80 KB
    cudaFuncSetAttribute(layer1_fused_kernel,
        cudaFuncAttributeMaxDynamicSharedMemorySize, smem_l1);
    cudaFuncSetAttribute(transform2_kernel,
        cudaFuncAttributeMaxDynamicSharedMemorySize, smem_t2);

    void* deg_out_addr = nullptr;
    void* deg_in_addr = nullptr;
    void* flag_addr = nullptr;
    cudaGetSymbolAddress(&deg_out_addr, g_deg_out);
    cudaGetSymbolAddress(&deg_in_addr, g_deg_in);
    cudaGetSymbolAddress(&flag_addr, g_scan_flag);
    cudaMemsetAsync(deg_out_addr, 0, NN * sizeof(int));
    cudaMemsetAsync(deg_in_addr, 0, NN * sizeof(int));
    cudaMemsetAsync(flag_addr, 0, SCAN_BLOCKS * sizeof(int));

    degree_kernel<<<(EE + 255) / 256, 256>>>(src, dst);
    scan_fused_kernel<<<SCAN_BLOCKS, 1024>>>();
    csr_scale_kernel<<<(EE + 255) / 256, 256>>>(src, dst, features);

    // launch 4 (PROFILED): fused layer-1 aggregate + GEMM + relu
    layer1_fused_kernel<<<NN / 32, 256, smem_l1>>>(W1, b1);

    dim3 tblock(32, 8);
    transform2_kernel<<<NN / 32, tblock, smem_t2>>>(W2);
    aggregate_kernel<<<(NN * 32 + 255) / 256, 256>>>(b2);

    // hybrid bitonic top-K
    topk_local_kernel<<<NBATCH * 8, 128>>>(b3, out);
    topk_global_phase_kernel<<<NBATCH * 32, 256>>>(4096, 2048);
    topk_merge_kernel<4096, false><<<NBATCH * 8, 128>>>();
    topk_global_phase_kernel<<<NBATCH * 32, 256>>>(8192, 4096);
    topk_global_phase_kernel<<<NBATCH * 32, 256>>>(8192, 2048);
    topk_merge_kernel<8192, false><<<NBATCH * 8, 128>>>();
    topk_global_phase_kernel<<<NBATCH * 32, 256>>>(16384, 8192);
    topk_global_phase_kernel<<<NBATCH * 32, 256>>>(16384, 4096);
    topk_global_phase_kernel<<<NBATCH * 32, 256>>>(16384, 2048);
    topk_merge_kernel<16384, true><<<NBATCH * 8, 128>>>();

    final_gemm_kernel<<<250, 256>>>(W3, out);
}

// round 15
// speedup vs baseline: 1.0979x; 1.0137x over previous
#include <cuda_runtime.h>
#include <cstdint>

#define NN    100000
#define EE    1600000
#define HIDD  128
#define INDIM 64
#define NBATCH 8
#define KTOP  5000
#define NPER  12500
#define NCLS  18
#define SORTN 16384
#define TILE  2048
#define SCAN_BLOCKS 98   // ceil(100000 / 1024)

// packed f32x2 add: per-lane IEEE rn, bit-identical to scalar FADD
#define FADD2(acc, b)      asm("add.rn.f32x2 %0, %0, %1;" : "+l"(acc) : "l"(b))
#define UNPACK2(lo, hi, v) asm("mov.b64 {%0, %1}, %2;" : "=f"(lo), "=f"(hi) : "l"(v))

// smem bank swizzle for the sort (alters only low 4 bits; bijective in-tile)
#define PHYS(i) ((i) ^ (((i) >> 4) & 15))

// 4 FMAs of scalar x into float4 acc
#define FMA4(acc, xs_, wv_) \
    acc.x += (xs_) * (wv_).x; acc.y += (xs_) * (wv_).y; \
    acc.z += (xs_) * (wv_).z; acc.w += (xs_) * (wv_).w;

// ---------------- scratch (device globals; referenced ONLY from device code) --
__device__ float g_t[(size_t)NN * HIDD];
__device__ float g_h[(size_t)NN * HIDD];
__device__ float g_norm_src[NN];
__device__ float g_norm_dst[NN];
__device__ int   g_deg_out[NN];
__device__ int   g_deg_in[NN];
__device__ int   g_row_start[NN + 1];
__device__ int   g_cursor[NN];
__device__ int   g_csr_src[EE];
__device__ int   g_topk[NBATCH * KTOP];
__device__ int   g_scan_agg[SCAN_BLOCKS];
__device__ int   g_scan_flag[SCAN_BLOCKS];
__device__ unsigned long long g_keys[NBATCH * SORTN];   // 1 MB sort scratch

// ---------------- degree (launch 1) -------------------------------------------
__global__ void degree_kernel(const int* __restrict__ src, const int* __restrict__ dst) {
    int e = blockIdx.x * blockDim.x + threadIdx.x;
    if (e < EE) {
        atomicAdd(&g_deg_out[src[e]], 1);
        atomicAdd(&g_deg_in[dst[e]], 1);
    }
}

// ---------------- single-kernel scan + norms (launch 2) ------------------------
__global__ void scan_fused_kernel() {
    __shared__ int sh[1024];
    __shared__ int red[128];
    int tid = threadIdx.x, b = blockIdx.x;
    int i = b * 1024 + tid;
    int v = (i < NN) ? g_deg_in[i] : 0;

    sh[tid] = v;
    __syncthreads();
    #pragma unroll
    for (int off = 512; off > 0; off >>= 1) {
        if (tid < off) sh[tid] += sh[tid + off];
        __syncthreads();
    }
    int bsum = sh[0];
    __syncthreads();
    if (tid == 0) {
        *(volatile int*)&g_scan_agg[b] = bsum;
        __threadfence();
        *(volatile int*)&g_scan_flag[b] = 1;
    }

    if (tid < 128) {
        int val = 0;
        if (tid < b) {
            while (*(volatile int*)&g_scan_flag[tid] == 0) {}
            val = *(volatile int*)&g_scan_agg[tid];
        }
        red[tid] = val;
    }
    __syncthreads();
    #pragma unroll
    for (int off = 64; off > 0; off >>= 1) {
        if (tid < off) red[tid] += red[tid + off];
        __syncthreads();
    }
    int offset = red[0];
    __syncthreads();

    sh[tid] = v;
    __syncthreads();
    #pragma unroll
    for (int o = 1; o < 1024; o <<= 1) {
        int add = (tid >= o) ? sh[tid - o] : 0;
        __syncthreads();
        sh[tid] += add;
        __syncthreads();
    }
    if (i < NN) {
        int excl = offset + sh[tid] - v;
        g_row_start[i] = excl;
        g_cursor[i] = excl;
        g_norm_dst[i] = rsqrtf((float)max(v, 1));
        g_norm_src[i] = rsqrtf((float)max(g_deg_out[i], 1));
    }
    if (b == SCAN_BLOCKS - 1 && tid == 0)
        g_row_start[NN] = offset + bsum;
}

// ---------------- csr fill + src scaling fused (launch 3) ----------------------
__global__ void csr_scale_kernel(const int* __restrict__ src,
                                 const int* __restrict__ dst,
                                 const float* __restrict__ x) {
    int e = blockIdx.x * blockDim.x + threadIdx.x;
    if (e < EE) {
        int d = dst[e];
        int pos = atomicAdd(&g_cursor[d], 1);
        g_csr_src[pos] = src[e];
        int node = e >> 4;
        float ns = g_norm_src[node];
        float4 v = *(const float4*)&x[e * 4];
        v.x *= ns; v.y *= ns; v.z *= ns; v.w *= ns;
        *(float4*)&g_t[e * 4] = v;
    }
}

// ---------------- layer-1 fused: aggregate(64) + GEMM + relu (launch 4) --------
// vectorized-x Phase B; launch bounds pin 5 blocks/SM (smem-limited anyway)
__global__ void __launch_bounds__(256, 5)
layer1_fused_kernel(const float* __restrict__ W, const float* __restrict__ bias) {
    extern __shared__ float sh[];
    float* Ws = sh;                  // 64*128
    float* xs = sh + 64 * 128;       // 32*64
    int tid = threadIdx.x;
    int lane = tid & 31, wid = tid >> 5;
    int base = blockIdx.x * 32;

    for (int i = tid * 4; i < 64 * 128; i += 256 * 4)
        *(float4*)&Ws[i] = *(const float4*)&W[i];

    // Phase A: gather+aggregate 4 nodes per warp (half-warp rows)
    int half = lane >> 4;
    unsigned hoff = (unsigned)(lane & 15) * 4u;
    const float* tbase = (const float*)g_t;
    #pragma unroll
    for (int ni = 0; ni < 4; ni++) {
        int node = base + wid * 4 + ni;
        int s0 = g_row_start[node], s1 = g_row_start[node + 1];
        unsigned long long a0 = 0, a1 = 0, b0 = 0, b1 = 0;
        for (int bb = s0; bb < s1; bb += 32) {
            int my = (bb + lane < s1) ? g_csr_src[bb + lane] : 0;
            int cnt = min(32, s1 - bb);
            int t = 0;
            for (; t + 4 <= cnt; t += 4) {
                int sA = __shfl_sync(0xffffffffu, my, t + half);
                int sB = __shfl_sync(0xffffffffu, my, t + 2 + half);
                ulonglong2 uA = *(const ulonglong2*)&tbase[(unsigned)sA * 64u + hoff];
                ulonglong2 uB = *(const ulonglong2*)&tbase[(unsigned)sB * 64u + hoff];
                FADD2(a0, uA.x); FADD2(a1, uA.y);
                FADD2(b0, uB.x); FADD2(b1, uB.y);
            }
            for (; t + 2 <= cnt; t += 2) {
                int s = __shfl_sync(0xffffffffu, my, t + half);
                ulonglong2 u = *(const ulonglong2*)&tbase[(unsigned)s * 64u + hoff];
                FADD2(a0, u.x); FADD2(a1, u.y);
            }
            if (t < cnt) {
                int s = __shfl_sync(0xffffffffu, my, t);
                if (half == 0) {
                    ulonglong2 u = *(const ulonglong2*)&tbase[(unsigned)s * 64u + hoff];
                    FADD2(b0, u.x); FADD2(b1, u.y);
                }
            }
        }
        FADD2(a0, b0); FADD2(a1, b1);
        float4 r;
        UNPACK2(r.x, r.y, a0); UNPACK2(r.z, r.w, a1);
        r.x += __shfl_xor_sync(0xffffffffu, r.x, 16);
        r.y += __shfl_xor_sync(0xffffffffu, r.y, 16);
        r.z += __shfl_xor_sync(0xffffffffu, r.z, 16);
        r.w += __shfl_xor_sync(0xffffffffu, r.w, 16);
        if (half == 0)
            *(float4*)&xs[(unsigned)(wid * 4 + ni) * 64u + hoff] = r;
    }
    __syncthreads();

    // Phase B: GEMM, k chunked by 4 with float4 x loads (broadcast LDS.128)
    int tx = lane, ty = wid;
    float4 acc0 = make_float4(0.f, 0.f, 0.f, 0.f);
    float4 acc1 = make_float4(0.f, 0.f, 0.f, 0.f);
    float4 acc2 = make_float4(0.f, 0.f, 0.f, 0.f);
    float4 acc3 = make_float4(0.f, 0.f, 0.f, 0.f);
    const float* x0p = &xs[(ty * 4 + 0) * 64];
    const float* x1p = &xs[(ty * 4 + 1) * 64];
    const float* x2p = &xs[(ty * 4 + 2) * 64];
    const float* x3p = &xs[(ty * 4 + 3) * 64];
    #pragma unroll 2
    for (int kc = 0; kc < 64; kc += 4) {
        float4 xv0 = *(const float4*)&x0p[kc];
        float4 xv1 = *(const float4*)&x1p[kc];
        float4 xv2 = *(const float4*)&x2p[kc];
        float4 xv3 = *(const float4*)&x3p[kc];
        const float* wb = &Ws[kc * 128 + tx * 4];
        float4 wv0 = *(const float4*)&wb[0];
        float4 wv1 = *(const float4*)&wb[128];
        float4 wv2 = *(const float4*)&wb[256];
        float4 wv3 = *(const float4*)&wb[384];
        FMA4(acc0, xv0.x, wv0); FMA4(acc1, xv1.x, wv0);
        FMA4(acc2, xv2.x, wv0); FMA4(acc3, xv3.x, wv0);
        FMA4(acc0, xv0.y, wv1); FMA4(acc1, xv1.y, wv1);
        FMA4(acc2, xv2.y, wv1); FMA4(acc3, xv3.y, wv1);
        FMA4(acc0, xv0.z, wv2); FMA4(acc1, xv1.z, wv2);
        FMA4(acc2, xv2.z, wv2); FMA4(acc3, xv3.z, wv2);
        FMA4(acc0, xv0.w, wv3); FMA4(acc1, xv1.w, wv3);
        FMA4(acc2, xv2.w, wv3); FMA4(acc3, xv3.w, wv3);
    }

    int n0 = base + ty * 4;
    float4 accs[4] = {acc0, acc1, acc2, acc3};
    float4 b = *(const float4*)&bias[tx * 4];
    #pragma unroll
    for (int i = 0; i < 4; i++) {
        float nd = g_norm_dst[n0 + i];
        float4 a = accs[i];
        float4 r;
        r.x = fmaxf(a.x * nd + b.x, 0.f);
        r.y = fmaxf(a.y * nd + b.y, 0.f);
        r.z = fmaxf(a.z * nd + b.z, 0.f);
        r.w = fmaxf(a.w * nd + b.w, 0.f);
        *(float4*)&g_h[(size_t)(n0 + i) * 128 + tx * 4] = r;
    }
}

// ---------------- transform (layer 2): vectorized-x GEMM -> g_t ---------------
__global__ void transform2_kernel(const float* __restrict__ W) {
    extern __shared__ float sh[];
    float* Ws = sh;                  // 128*128
    float* xs = sh + 128 * 128;      // 32*128
    int tx = threadIdx.x, ty = threadIdx.y;
    int tid = ty * 32 + tx;
    for (int i = tid * 4; i < 128 * 128; i += 256 * 4)
        *(float4*)&Ws[i] = *(const float4*)&W[i];
    int base = blockIdx.x * 32;
    for (int i = tid * 4; i < 32 * 128; i += 256 * 4)
        *(float4*)&xs[i] = *(const float4*)&g_h[(size_t)base * 128 + i];
    __syncthreads();

    float4 acc0 = make_float4(0.f, 0.f, 0.f, 0.f);
    float4 acc1 = make_float4(0.f, 0.f, 0.f, 0.f);
    float4 acc2 = make_float4(0.f, 0.f, 0.f, 0.f);
    float4 acc3 = make_float4(0.f, 0.f, 0.f, 0.f);
    const float* x0p = &xs[(ty * 4 + 0) * 128];
    const float* x1p = &xs[(ty * 4 + 1) * 128];
    const float* x2p = &xs[(ty * 4 + 2) * 128];
    const float* x3p = &xs[(ty * 4 + 3) * 128];
    #pragma unroll 2
    for (int kc = 0; kc < 128; kc += 4) {
        float4 xv0 = *(const float4*)&x0p[kc];
        float4 xv1 = *(const float4*)&x1p[kc];
        float4 xv2 = *(const float4*)&x2p[kc];
        float4 xv3 = *(const float4*)&x3p[kc];
        const float* wb = &Ws[kc * 128 + tx * 4];
        float4 wv0 = *(const float4*)&wb[0];
        float4 wv1 = *(const float4*)&wb[128];
        float4 wv2 = *(const float4*)&wb[256];
        float4 wv3 = *(const float4*)&wb[384];
        FMA4(acc0, xv0.x, wv0); FMA4(acc1, xv1.x, wv0);
        FMA4(acc2, xv2.x, wv0); FMA4(acc3, xv3.x, wv0);
        FMA4(acc0, xv0.y, wv1); FMA4(acc1, xv1.y, wv1);
        FMA4(acc2, xv2.y, wv1); FMA4(acc3, xv3.y, wv1);
        FMA4(acc0, xv0.z, wv2); FMA4(acc1, xv1.z, wv2);
        FMA4(acc2, xv2.z, wv2); FMA4(acc3, xv3.z, wv2);
        FMA4(acc0, xv0.w, wv3); FMA4(acc1, xv1.w, wv3);
        FMA4(acc2, xv2.w, wv3); FMA4(acc3, xv3.w, wv3);
    }

    int n0 = base + ty * 4;
    float4 accs[4] = {acc0, acc1, acc2, acc3};
    #pragma unroll
    for (int i = 0; i < 4; i++) {
        float ns = g_norm_src[n0 + i];
        float4 a = accs[i];
        a.x *= ns; a.y *= ns; a.z *= ns; a.w *= ns;
        *(float4*)&g_t[(size_t)(n0 + i) * 128 + tx * 4] = a;
    }
}

// ---------------- 128-dim aggregate (layer 2): occupancy-capped ----------------
__global__ void __launch_bounds__(256, 6)
aggregate_kernel(const float* __restrict__ bias) {
    int gtid = blockIdx.x * blockDim.x + threadIdx.x;
    int node = gtid >> 5;
    int lane = gtid & 31;
    if (node >= NN) return;
    unsigned loff = (unsigned)lane * 4u;
    int s0 = g_row_start[node], s1 = g_row_start[node + 1];
    unsigned long long a0 = 0, a1 = 0, b0 = 0, b1 = 0;
    const float* tbase = (const float*)g_t;
    for (int base = s0; base < s1; base += 32) {
        int my = (base + lane < s1) ? g_csr_src[base + lane] : 0;
        int cnt = min(32, s1 - base);
        int t = 0;
        for (; t + 2 <= cnt; t += 2) {
            int sA = __shfl_sync(0xffffffffu, my, t);
            int sB = __shfl_sync(0xffffffffu, my, t + 1);
            ulonglong2 uA = *(const ulonglong2*)&tbase[(unsigned)sA * 128u + loff];
            ulonglong2 uB = *(const ulonglong2*)&tbase[(unsigned)sB * 128u + loff];
            FADD2(a0, uA.x); FADD2(a1, uA.y);
            FADD2(b0, uB.x); FADD2(b1, uB.y);
        }
        if (t < cnt) {
            int s = __shfl_sync(0xffffffffu, my, t);
            ulonglong2 u = *(const ulonglong2*)&tbase[(unsigned)s * 128u + loff];
            FADD2(a0, u.x); FADD2(a1, u.y);
        }
    }
    FADD2(a0, b0); FADD2(a1, b1);
    float4 acc;
    UNPACK2(acc.x, acc.y, a0); UNPACK2(acc.z, acc.w, a1);
    float nd = g_norm_dst[node];
    float4 b = *(const float4*)&bias[loff];
    float4 r;
    r.x = fmaxf(acc.x * nd + b.x, 0.f);
    r.y = fmaxf(acc.y * nd + b.y, 0.f);
    r.z = fmaxf(acc.z * nd + b.z, 0.f);
    r.w = fmaxf(acc.w * nd + b.w, 0.f);
    *(float4*)&g_h[(unsigned)node * 128u + loff] = r;
}

// =================== hybrid bitonic top-K (bit-identical network) ==============
__global__ void topk_local_kernel(const float* __restrict__ b3, float* __restrict__ out) {
    __shared__ unsigned long long s[TILE];
    int blk = blockIdx.x;
    int b = blk >> 3, t = blk & 7;
    int tid = threadIdx.x;            // 128 threads
    int gbase = t * TILE;
    if (blk == 0) {
        for (int i = tid; i < NBATCH * NCLS; i += 128)
            out[i] = b3[i % NCLS];
    }

    for (int i = tid; i < TILE; i += 128) {
        int gi = gbase + i;
        unsigned long long key;
        if (gi < NPER) {
            float f = g_h[((size_t)(b * NPER + gi)) * 128 + 127];
            unsigned bits = __float_as_uint(f);
            unsigned m = ((int)bits < 0) ? ~bits : (bits ^ 0x80000000u);
            key = (((unsigned long long)(~m)) << 32) | (unsigned)gi;
        } else {
            key = 0xFFFFFFFFFFFFFFFFull;
        }
        s[PHYS(i)] = key;
    }
    __syncthreads();

    unsigned long long r[16];
    int base16 = tid * 16;

    #pragma unroll
    for (int i = 0; i < 16; i++) r[i] = s[PHYS(base16 + i)];
    #pragma unroll
    for (int k = 2; k <= 16; k <<= 1) {
        #pragma unroll
        for (int j = k >> 1; j > 0; j >>= 1) {
            #pragma unroll
            for (int i = 0; i < 16; i++) {
                if ((i & j) == 0) {
                    bool up = (((gbase + base16 + i) & k) == 0);
                    unsigned long long lo = r[i], hi = r[i | j];
                    if ((lo > hi) == up) { r[i] = hi; r[i | j] = lo; }
                }
            }
        }
    }
    #pragma unroll
    for (int i = 0; i < 16; i++) s[PHYS(base16 + i)] = r[i];
    __syncthreads();

    for (int k = 32; k <= TILE; k <<= 1) {
        for (int j = k >> 1; j >= 16; j >>= 1) {
            #pragma unroll
            for (int q = 0; q < TILE / 2 / 128; q++) {
                int p = tid + q * 128;
                int idx = ((p & ~(j - 1)) << 1) | (p & (j - 1));
                int partner = idx + j;
                bool up = (((gbase + idx) & k) == 0);
                unsigned long long a = s[PHYS(idx)], c = s[PHYS(partner)];
                if ((a > c) == up) { s[PHYS(idx)] = c; s[PHYS(partner)] = a; }
            }
            __syncthreads();
        }
        {
            bool up = (((gbase + base16) & k) == 0);
            #pragma unroll
            for (int i = 0; i < 16; i++) r[i] = s[PHYS(base16 + i)];
            #pragma unroll
            for (int j = 8; j > 0; j >>= 1) {
                #pragma unroll
                for (int i = 0; i < 16; i++) {
                    if ((i & j) == 0) {
                        unsigned long long lo = r[i], hi = r[i | j];
                        if ((lo > hi) == up) { r[i] = hi; r[i | j] = lo; }
                    }
                }
            }
            #pragma unroll
            for (int i = 0; i < 16; i++) s[PHYS(base16 + i)] = r[i];
            __syncthreads();
        }
    }

    for (int i = tid; i < TILE; i += 128)
        g_keys[b * SORTN + gbase + i] = s[PHYS(i)];
}

__global__ void topk_global_phase_kernel(int k, int j) {
    int gt = blockIdx.x * blockDim.x + threadIdx.x;   // 8 * 8192 threads
    int b = gt >> 13;
    int p = gt & 8191;
    int idx = ((p & ~(j - 1)) << 1) | (p & (j - 1));
    int partner = idx + j;
    bool up = ((idx & k) == 0);
    unsigned long long* keys = &g_keys[(size_t)b * SORTN];
    unsigned long long a = keys[idx], c = keys[partner];
    if ((a > c) == up) { keys[idx] = c; keys[partner] = a; }
}

template <int KSTAGE, bool FINAL>
__global__ void topk_merge_kernel() {
    __shared__ unsigned long long s[TILE];
    int blk = blockIdx.x;
    int b = blk >> 3, t = blk & 7;
    int tid = threadIdx.x;            // 128 threads
    int gbase = t * TILE;
    const bool up = ((gbase & KSTAGE) == 0);

    for (int i = tid; i < TILE; i += 128)
        s[PHYS(i)] = g_keys[b * SORTN + gbase + i];
    __syncthreads();

    for (int j = 1024; j >= 16; j >>= 1) {
        #pragma unroll
        for (int q = 0; q < TILE / 2 / 128; q++) {
            int p = tid + q * 128;
            int idx = ((p & ~(j - 1)) << 1) | (p & (j - 1));
            int partner = idx + j;
            unsigned long long a = s[PHYS(idx)], c = s[PHYS(partner)];
            if ((a > c) == up) { s[PHYS(idx)] = c; s[PHYS(partner)] = a; }
        }
        __syncthreads();
    }

    unsigned long long r[16];
    int base16 = tid * 16;
    #pragma unroll
    for (int i = 0; i < 16; i++) r[i] = s[PHYS(base16 + i)];
    #pragma unroll
    for (int j = 8; j > 0; j >>= 1) {
        #pragma unroll
        for (int i = 0; i < 16; i++) {
            if ((i & j) == 0) {
                unsigned long long lo = r[i], hi = r[i | j];
                if ((lo > hi) == up) { r[i] = hi; r[i | j] = lo; }
            }
        }
    }
    if (FINAL) {
        #pragma unroll
        for (int i = 0; i < 16; i++) {
            int gpos = gbase + base16 + i;
            if (gpos < KTOP)
                g_topk[b * KTOP + gpos] = b * NPER + (int)(r[i] & 0xFFFFFFFFu);
        }
    } else {
        #pragma unroll
        for (int i = 0; i < 16; i++)
            g_keys[b * SORTN + gbase + base16 + i] = r[i];
    }
}

// ---------------- readout ------------------------------------------------------
__global__ void final_gemm_kernel(const float* __restrict__ W3, float* __restrict__ out) {
    int w = threadIdx.x >> 5, lane = threadIdx.x & 31;
    const int KTOT = KTOP * 128;
    int per = KTOT / gridDim.x;
    int k0 = blockIdx.x * per, k1 = k0 + per;
    float acc[NCLS];
    #pragma unroll
    for (int c = 0; c < NCLS; c++) acc[c] = 0.f;
    for (int k = k0 + lane; k < k1; k += 32) {
        int i = k >> 7, h = k & 127;
        int node = g_topk[w * KTOP + i];
        float x = g_h[(size_t)node * 128 + h];
        const float* wrow = &W3[(size_t)k * NCLS];
        #pragma unroll
        for (int c = 0; c < NCLS; c++) acc[c] += x * wrow[c];
    }
    #pragma unroll
    for (int c = 0; c < NCLS; c++) {
        float v = acc[c];
        #pragma unroll
        for (int o = 16; o > 0; o >>= 1) v += __shfl_down_sync(0xffffffffu, v, o);
        if (lane == 0) atomicAdd(&out[w * NCLS + c], v);
    }
}

// ---------------- launch ------------------------------------------------------
extern "C" void kernel_launch(void* const* d_in, const int* in_sizes, int n_in,
                              void* d_out, int out_size) {
    const float* features = (const float*)d_in[0];
    const int*   src      = (const int*)d_in[1];
    const int*   dst      = (const int*)d_in[2];
    const float* W1       = (const float*)d_in[3];
    const float* b1       = (const float*)d_in[4];
    const float* W2       = (const float*)d_in[5];
    const float* b2       = (const float*)d_in[6];
    const float* W3       = (const float*)d_in[7];
    const float* b3       = (const float*)d_in[8];
    float* out = (float*)d_out;

    const int smem_l1 = (64 * 128 + 32 * 64) * 4;    // 40 KB
    const int smem_t2 = (128 * 128 + 32 * 128) * 4;  // 80 KB
    cudaFuncSetAttribute(layer1_fused_kernel,
        cudaFuncAttributeMaxDynamicSharedMemorySize, smem_l1);
    cudaFuncSetAttribute(transform2_kernel,
        cudaFuncAttributeMaxDynamicSharedMemorySize, smem_t2);

    void* deg_out_addr = nullptr;
    void* deg_in_addr = nullptr;
    void* flag_addr = nullptr;
    cudaGetSymbolAddress(&deg_out_addr, g_deg_out);
    cudaGetSymbolAddress(&deg_in_addr, g_deg_in);
    cudaGetSymbolAddress(&flag_addr, g_scan_flag);
    cudaMemsetAsync(deg_out_addr, 0, NN * sizeof(int));
    cudaMemsetAsync(deg_in_addr, 0, NN * sizeof(int));
    cudaMemsetAsync(flag_addr, 0, SCAN_BLOCKS * sizeof(int));

    degree_kernel<<<(EE + 255) / 256, 256>>>(src, dst);
    scan_fused_kernel<<<SCAN_BLOCKS, 1024>>>();
    csr_scale_kernel<<<(EE + 255) / 256, 256>>>(src, dst, features);

    // launch 4 (PROFILED): fused layer-1 aggregate + GEMM + relu
    layer1_fused_kernel<<<NN / 32, 256, smem_l1>>>(W1, b1);

    dim3 tblock(32, 8);
    transform2_kernel<<<NN / 32, tblock, smem_t2>>>(W2);
    aggregate_kernel<<<(NN * 32 + 255) / 256, 256>>>(b2);

    // hybrid bitonic top-K
    topk_local_kernel<<<NBATCH * 8, 128>>>(b3, out);
    topk_global_phase_kernel<<<NBATCH * 32, 256>>>(4096, 2048);
    topk_merge_kernel<4096, false><<<NBATCH * 8, 128>>>();
    topk_global_phase_kernel<<<NBATCH * 32, 256>>>(8192, 4096);
    topk_global_phase_kernel<<<NBATCH * 32, 256>>>(8192, 2048);
    topk_merge_kernel<8192, false><<<NBATCH * 8, 128>>>();
    topk_global_phase_kernel<<<NBATCH * 32, 256>>>(16384, 8192);
    topk_global_phase_kernel<<<NBATCH * 32, 256>>>(16384, 4096);
    topk_global_phase_kernel<<<NBATCH * 32, 256>>>(16384, 2048);
    topk_merge_kernel<16384, true><<<NBATCH * 8, 128>>>();

    final_gemm_kernel<<<250, 256>>>(W3, out);
}